// round 4
// baseline (speedup 1.0000x reference)
#include <cuda_runtime.h>
#include <cuda_bf16.h>
#include <cstdint>
#include <math.h>

#define DI __device__ __forceinline__

static constexpr int T_  = 8192;
static constexpr int H_  = 2048;
static constexpr int O_  = 2048;
static constexpr int E_  = 8;
static constexpr int R_  = 16;
static constexpr int ER_ = 128;
static constexpr float ALPHA_ = 16.0f;

// ---------------- scratch (__device__ globals) ------------------------------
__device__ __align__(256) __nv_bfloat16 g_xhi[T_ * H_];
__device__ __align__(256) __nv_bfloat16 g_xlo[T_ * H_];
__device__ __align__(256) __nv_bfloat16 g_whi[O_ * H_];
__device__ __align__(256) __nv_bfloat16 g_wlo[O_ * H_];
__device__ __align__(256) __nv_bfloat16 g_ahi[ER_ * H_];
__device__ __align__(256) __nv_bfloat16 g_alo[ER_ * H_];
__device__ __align__(256) __nv_bfloat16 g_bchi[O_ * ER_];
__device__ __align__(256) __nv_bfloat16 g_bclo[O_ * ER_];
__device__ __align__(256) __nv_bfloat16 g_hwhi[T_ * ER_];
__device__ __align__(256) __nv_bfloat16 g_hwlo[T_ * ER_];
__device__ __align__(256) float         g_wmat[T_ * E_];

// ---------------- PTX helpers (base-ISA only: sm_80-era) ---------------------
DI uint32_t smem_u32(const void* p) {
    uint32_t a;
    asm("{ .reg .u64 t; cvta.to.shared.u64 t, %1; cvt.u32.u64 %0, t; }"
        : "=r"(a) : "l"(p));
    return a;
}
DI void cpasync16(uint32_t dst, const void* src) {
    asm volatile("cp.async.cg.shared.global [%0], [%1], 16;" :: "r"(dst), "l"(src));
}
DI void cp_commit() { asm volatile("cp.async.commit_group;" ::: "memory"); }
template <int N> DI void cp_wait() {
    asm volatile("cp.async.wait_group %0;" :: "n"(N) : "memory");
}
DI void ldm_x4(uint32_t* r, uint32_t a) {
    asm volatile("ldmatrix.sync.aligned.m8n8.x4.shared.b16 {%0,%1,%2,%3}, [%4];"
                 : "=r"(r[0]), "=r"(r[1]), "=r"(r[2]), "=r"(r[3]) : "r"(a));
}
DI void mma_bf16(float* c, const uint32_t* a, uint32_t b0, uint32_t b1) {
    asm volatile(
        "mma.sync.aligned.m16n8k16.row.col.f32.bf16.bf16.f32 "
        "{%0,%1,%2,%3}, {%4,%5,%6,%7}, {%8,%9}, {%0,%1,%2,%3};"
        : "+f"(c[0]), "+f"(c[1]), "+f"(c[2]), "+f"(c[3])
        : "r"(a[0]), "r"(a[1]), "r"(a[2]), "r"(a[3]), "r"(b0), "r"(b1));
}

// ---------------- conversion kernels -----------------------------------------
__global__ void k_split(const float* __restrict__ src, int n4, int sel) {
    __nv_bfloat16 *hi, *lo;
    if (sel == 0)      { hi = g_xhi; lo = g_xlo; }
    else if (sel == 1) { hi = g_whi; lo = g_wlo; }
    else               { hi = g_ahi; lo = g_alo; }
    int i = blockIdx.x * blockDim.x + threadIdx.x;
    if (i >= n4) return;
    float4 v = reinterpret_cast<const float4*>(src)[i];
    float a0 = v.x, a1 = v.y, a2 = v.z, a3 = v.w;
    __nv_bfloat16 h0 = __float2bfloat16(a0), h1 = __float2bfloat16(a1);
    __nv_bfloat16 h2 = __float2bfloat16(a2), h3 = __float2bfloat16(a3);
    __nv_bfloat16 l0 = __float2bfloat16(a0 - __bfloat162float(h0));
    __nv_bfloat16 l1 = __float2bfloat16(a1 - __bfloat162float(h1));
    __nv_bfloat16 l2 = __float2bfloat16(a2 - __bfloat162float(h2));
    __nv_bfloat16 l3 = __float2bfloat16(a3 - __bfloat162float(h3));
    __nv_bfloat162 hp0(h0, h1), hp1(h2, h3), lp0(l0, l1), lp1(l2, l3);
    uint2 hv = make_uint2(*reinterpret_cast<uint32_t*>(&hp0), *reinterpret_cast<uint32_t*>(&hp1));
    uint2 lv = make_uint2(*reinterpret_cast<uint32_t*>(&lp0), *reinterpret_cast<uint32_t*>(&lp1));
    *reinterpret_cast<uint2*>(hi + (size_t)4 * i) = hv;
    *reinterpret_cast<uint2*>(lo + (size_t)4 * i) = lv;
}

__global__ void k_bcat(const float* __restrict__ Bsrc, int n) {
    int i = blockIdx.x * blockDim.x + threadIdx.x;
    if (i >= n) return;
    int o = i >> 7, j = i & 127, e = j >> 4, r = j & 15;
    float v = Bsrc[((size_t)e * O_ + o) * R_ + r];
    __nv_bfloat16 h = __float2bfloat16(v);
    g_bchi[i] = h;
    g_bclo[i] = __float2bfloat16(v - __bfloat162float(h));
}

// ---------------- router ------------------------------------------------------
static constexpr int R_GS = 2052;
static constexpr int R_SMEM = (8 * R_GS + 128) * 4;

__global__ void __launch_bounds__(128) k_router(const float* __restrict__ x,
                                                const float* __restrict__ gw) {
    extern __shared__ char smraw[];
    float* sg = reinterpret_cast<float*>(smraw);
    float* lsm = sg + 8 * R_GS;
    for (int i = threadIdx.x; i < E_ * H_; i += 128) {
        int e = i >> 11, h = i & 2047;
        sg[e * R_GS + h] = gw[i];
    }
    __syncthreads();
    int tok = threadIdx.x >> 3, e = threadIdx.x & 7;
    int tG = blockIdx.x * 16 + tok;
    const float4* xr = reinterpret_cast<const float4*>(x + (size_t)tG * H_);
    const float* ge = sg + e * R_GS;
    float s0 = 0.f, s1 = 0.f, s2 = 0.f, s3 = 0.f;
#pragma unroll 4
    for (int h4 = 0; h4 < H_ / 4; h4++) {
        float4 xv = xr[h4];
        s0 += xv.x * ge[h4 * 4 + 0];
        s1 += xv.y * ge[h4 * 4 + 1];
        s2 += xv.z * ge[h4 * 4 + 2];
        s3 += xv.w * ge[h4 * 4 + 3];
    }
    lsm[tok * 8 + e] = (s0 + s1) + (s2 + s3);
    __syncthreads();
    if (threadIdx.x < 16) {
        int t = threadIdx.x;
        float l[8], m = -1e30f;
#pragma unroll
        for (int i = 0; i < 8; i++) { l[i] = lsm[t * 8 + i]; m = fmaxf(m, l[i]); }
        float p[8], sum = 0.f;
#pragma unroll
        for (int i = 0; i < 8; i++) { p[i] = expf(l[i] - m); sum += p[i]; }
#pragma unroll
        for (int i = 0; i < 8; i++) p[i] /= sum;
        int i1 = 0;
#pragma unroll
        for (int i = 1; i < 8; i++) if (p[i] > p[i1]) i1 = i;
        int i2 = (i1 == 0) ? 1 : 0;
#pragma unroll
        for (int i = 0; i < 8; i++) if (i != i1 && p[i] > p[i2]) i2 = i;
        float ws = p[i1] + p[i2];
        int tg = blockIdx.x * 16 + t;
#pragma unroll
        for (int i = 0; i < 8; i++) {
            float v = (i == i1) ? ALPHA_ * p[i1] / ws
                    : (i == i2) ? ALPHA_ * p[i2] / ws : 0.f;
            g_wmat[tg * 8 + i] = v;
        }
    }
}

// ---------------- GEMM engine (mma.sync bf16, cp.async, 3-stage) --------------
// BM=BN=128, BK=32. smem tile: 128 rows x pitch 40 halves (80B) = 10240 B.
// pitch of 5 granules (gcd(5,8)=1) -> conflict-free ldmatrix.
static constexpr int PITCH_H = 40;                 // halves
static constexpr int PITCH_B = 80;                 // bytes
static constexpr int TILE_B  = 128 * PITCH_B;      // 10240
static constexpr int STAGE_B = 2 * TILE_B;         // A + B
static constexpr int G_SMEM  = 3 * STAGE_B;        // 61440

// MODE 0: main GEMM out = x@W^T + hw@Bcat^T   (NKT = 204)
// MODE 1: h GEMM   h = x@Aall^T               (NKT = 192)
template <int MODE>
DI void tile_src(int kt, int m0, int n0,
                 const __nv_bfloat16*& As, const __nv_bfloat16*& Bs, int& ld) {
    if (MODE == 1) {
        int pl = kt >> 6, k0 = (kt & 63) * 32;
        As = (pl == 1 ? g_xlo : g_xhi) + (size_t)m0 * H_ + k0;
        Bs = (pl == 2 ? g_alo : g_ahi) + (size_t)n0 * H_ + k0;
        ld = H_;
    } else {
        if (kt < 192) {
            int pl = kt >> 6, k0 = (kt & 63) * 32;
            As = (pl == 1 ? g_xlo : g_xhi) + (size_t)m0 * H_ + k0;
            Bs = (pl == 2 ? g_wlo : g_whi) + (size_t)n0 * H_ + k0;
            ld = H_;
        } else {
            int q = kt - 192, pl = q >> 2, k0 = (q & 3) * 32;
            As = (pl == 1 ? g_hwlo : g_hwhi) + (size_t)m0 * ER_ + k0;
            Bs = (pl == 2 ? g_bclo : g_bchi) + (size_t)n0 * ER_ + k0;
            ld = ER_;
        }
    }
}

template <int MODE>
DI void load_tile(uint32_t sbase, int stage, int kt, int m0, int n0, int tid) {
    const __nv_bfloat16 *As, *Bs;
    int ld;
    tile_src<MODE>(kt, m0, n0, As, Bs, ld);
    uint32_t sa = sbase + stage * STAGE_B;
    uint32_t sbB = sa + TILE_B;
#pragma unroll
    for (int j = 0; j < 2; j++) {
        int c = tid + j * 256;
        int row = c >> 2, kc = c & 3;
        uint32_t off = (uint32_t)row * PITCH_B + (uint32_t)kc * 16;
        cpasync16(sa + off, As + (size_t)row * ld + kc * 8);
        cpasync16(sbB + off, Bs + (size_t)row * ld + kc * 8);
    }
    cp_commit();
}

DI void compute_stage(uint32_t sa, uint32_t sbB, float acc[4][4][4],
                      uint32_t aoff, uint32_t boff) {
#pragma unroll
    for (int ks = 0; ks < 2; ks++) {
        uint32_t af[4][4], bfr[2][4];
#pragma unroll
        for (int mt = 0; mt < 4; mt++)
            ldm_x4(af[mt], sa + aoff + mt * (16 * PITCH_B) + ks * 32);
#pragma unroll
        for (int p = 0; p < 2; p++)
            ldm_x4(bfr[p], sbB + boff + p * (16 * PITCH_B) + ks * 32);
#pragma unroll
        for (int mt = 0; mt < 4; mt++)
#pragma unroll
            for (int nt = 0; nt < 4; nt++)
                mma_bf16(acc[mt][nt], af[mt],
                         bfr[nt >> 1][(nt & 1) * 2], bfr[nt >> 1][(nt & 1) * 2 + 1]);
    }
}

template <int MODE>
__global__ void __launch_bounds__(256, 2) k_gemm(float* __restrict__ out) {
    extern __shared__ __align__(128) char smem[];
    uint32_t sbase = smem_u32(smem);
    int tid = threadIdx.x, lane = tid & 31, w = tid >> 5;
    int warp_m = w >> 2, warp_n = w & 3;

    int m0, n0, NKT;
    if (MODE == 0) { m0 = (blockIdx.x & 63) * 128; n0 = (blockIdx.x >> 6) * 128; NKT = 204; }
    else           { m0 = blockIdx.x * 128;        n0 = 0;                       NKT = 192; }

    float acc[4][4][4];
#pragma unroll
    for (int a = 0; a < 4; a++)
#pragma unroll
        for (int b = 0; b < 4; b++)
#pragma unroll
            for (int c = 0; c < 4; c++) acc[a][b][c] = 0.f;

    // per-thread ldmatrix offsets (bytes within a tile)
    uint32_t aoff = (uint32_t)(warp_m * 64 + (lane & 7) + ((lane >> 3) & 1) * 8) * PITCH_B
                  + (uint32_t)(lane >> 4) * 16;
    uint32_t boff = (uint32_t)(warp_n * 32 + (lane & 7) + ((lane >> 4) & 1) * 8) * PITCH_B
                  + (uint32_t)((lane >> 3) & 1) * 16;

    load_tile<MODE>(sbase, 0, 0, m0, n0, tid);
    load_tile<MODE>(sbase, 1, 1, m0, n0, tid);

    int stage = 0;
    for (int kt = 0; kt < NKT; kt++) {
        if (kt + 2 < NKT) {
            int s2 = stage + 2; if (s2 >= 3) s2 -= 3;
            load_tile<MODE>(sbase, s2, kt + 2, m0, n0, tid);
            cp_wait<2>();
        } else if (kt + 1 < NKT) {
            cp_wait<1>();
        } else {
            cp_wait<0>();
        }
        __syncthreads();
        uint32_t sa = sbase + stage * STAGE_B;
        compute_stage(sa, sa + TILE_B, acc, aoff, boff);
        __syncthreads();
        if (++stage == 3) stage = 0;
    }

    if (MODE == 0) {
#pragma unroll
        for (int mt = 0; mt < 4; mt++) {
            int r0 = m0 + warp_m * 64 + mt * 16 + (lane >> 2);
#pragma unroll
            for (int nt = 0; nt < 4; nt++) {
                int col = n0 + warp_n * 32 + nt * 8 + (lane & 3) * 2;
                float2 v01 = make_float2(acc[mt][nt][0], acc[mt][nt][1]);
                float2 v23 = make_float2(acc[mt][nt][2], acc[mt][nt][3]);
                *reinterpret_cast<float2*>(out + (size_t)r0 * O_ + col) = v01;
                *reinterpret_cast<float2*>(out + (size_t)(r0 + 8) * O_ + col) = v23;
            }
        }
    } else {
#pragma unroll
        for (int mt = 0; mt < 4; mt++) {
            int t0 = m0 + warp_m * 64 + mt * 16 + (lane >> 2);
#pragma unroll
            for (int nt = 0; nt < 4; nt++) {
                int j = warp_n * 32 + nt * 8 + (lane & 3) * 2;
#pragma unroll
                for (int half = 0; half < 2; half++) {
                    int t = t0 + half * 8;
                    float wm = g_wmat[t * 8 + (j >> 4)];
                    float h0 = acc[mt][nt][half * 2 + 0] * wm;
                    float h1 = acc[mt][nt][half * 2 + 1] * wm;
                    __nv_bfloat16 b0 = __float2bfloat16(h0);
                    __nv_bfloat16 b1 = __float2bfloat16(h1);
                    __nv_bfloat16 c0 = __float2bfloat16(h0 - __bfloat162float(b0));
                    __nv_bfloat16 c1 = __float2bfloat16(h1 - __bfloat162float(b1));
                    __nv_bfloat162 hp(b0, b1), lp(c0, c1);
                    *reinterpret_cast<uint32_t*>(g_hwhi + (size_t)t * ER_ + j) =
                        *reinterpret_cast<uint32_t*>(&hp);
                    *reinterpret_cast<uint32_t*>(g_hwlo + (size_t)t * ER_ + j) =
                        *reinterpret_cast<uint32_t*>(&lp);
                }
            }
        }
    }
}

// ---------------- launch ------------------------------------------------------
extern "C" void kernel_launch(void* const* d_in, const int* in_sizes, int n_in,
                              void* d_out, int out_size) {
    const float* x  = (const float*)d_in[0];   // [4,2048,2048]
    const float* W  = (const float*)d_in[1];   // [2048,2048]
    const float* gw = (const float*)d_in[2];   // [8,2048]
    const float* A  = (const float*)d_in[3];   // [8,16,2048]
    const float* B  = (const float*)d_in[4];   // [8,2048,16]
    float* out = (float*)d_out;

    cudaFuncSetAttribute(k_router,  cudaFuncAttributeMaxDynamicSharedMemorySize, R_SMEM);
    cudaFuncSetAttribute(k_gemm<0>, cudaFuncAttributeMaxDynamicSharedMemorySize, G_SMEM);
    cudaFuncSetAttribute(k_gemm<1>, cudaFuncAttributeMaxDynamicSharedMemorySize, G_SMEM);

    {
        int n4 = (T_ * H_) / 4;
        k_split<<<(n4 + 255) / 256, 256>>>(x, n4, 0);
        n4 = (O_ * H_) / 4;
        k_split<<<(n4 + 255) / 256, 256>>>(W, n4, 1);
        n4 = (ER_ * H_) / 4;
        k_split<<<(n4 + 255) / 256, 256>>>(A, n4, 2);
        int n = O_ * ER_;
        k_bcat<<<(n + 255) / 256, 256>>>(B, n);
    }
    k_router<<<T_ / 16, 128, R_SMEM>>>(x, gw);
    k_gemm<1><<<T_ / 128, 256, G_SMEM>>>(nullptr);
    k_gemm<0><<<(T_ / 128) * (O_ / 128), 256, G_SMEM>>>(out);
}

// round 5
// speedup vs baseline: 1.9788x; 1.9788x over previous
#include <cuda_runtime.h>
#include <cuda_bf16.h>
#include <cstdint>
#include <math.h>

#define DI __device__ __forceinline__

static constexpr int T_  = 8192;
static constexpr int H_  = 2048;
static constexpr int O_  = 2048;
static constexpr int E_  = 8;
static constexpr int R_  = 16;
static constexpr int ER_ = 128;
static constexpr float ALPHA_ = 16.0f;

// ---------------- scratch (__device__ globals) ------------------------------
__device__ __align__(256) __nv_bfloat16 g_xhi[T_ * H_];
__device__ __align__(256) __nv_bfloat16 g_xlo[T_ * H_];
__device__ __align__(256) __nv_bfloat16 g_whi[O_ * H_];
__device__ __align__(256) __nv_bfloat16 g_wlo[O_ * H_];
__device__ __align__(256) __nv_bfloat16 g_ahi[ER_ * H_];
__device__ __align__(256) __nv_bfloat16 g_alo[ER_ * H_];
__device__ __align__(256) __nv_bfloat16 g_bchi[O_ * ER_];
__device__ __align__(256) __nv_bfloat16 g_bclo[O_ * ER_];
__device__ __align__(256) __nv_bfloat16 g_hwhi[T_ * ER_];
__device__ __align__(256) __nv_bfloat16 g_hwlo[T_ * ER_];
__device__ __align__(256) float         g_wmat[T_ * E_];

// ---------------- PTX helpers (base-ISA only) --------------------------------
DI uint32_t smem_u32(const void* p) {
    uint32_t a;
    asm("{ .reg .u64 t; cvta.to.shared.u64 t, %1; cvt.u32.u64 %0, t; }"
        : "=r"(a) : "l"(p));
    return a;
}
DI void cpasync16(uint32_t dst, const void* src) {
    asm volatile("cp.async.cg.shared.global [%0], [%1], 16;" :: "r"(dst), "l"(src));
}
DI void cp_commit() { asm volatile("cp.async.commit_group;" ::: "memory"); }
template <int N> DI void cp_wait() {
    asm volatile("cp.async.wait_group %0;" :: "n"(N) : "memory");
}
DI void ldm_x4(uint32_t* r, uint32_t a) {
    asm volatile("ldmatrix.sync.aligned.m8n8.x4.shared.b16 {%0,%1,%2,%3}, [%4];"
                 : "=r"(r[0]), "=r"(r[1]), "=r"(r[2]), "=r"(r[3]) : "r"(a));
}
DI void mma_bf16(float* c, const uint32_t* a, uint32_t b0, uint32_t b1) {
    asm volatile(
        "mma.sync.aligned.m16n8k16.row.col.f32.bf16.bf16.f32 "
        "{%0,%1,%2,%3}, {%4,%5,%6,%7}, {%8,%9}, {%0,%1,%2,%3};"
        : "+f"(c[0]), "+f"(c[1]), "+f"(c[2]), "+f"(c[3])
        : "r"(a[0]), "r"(a[1]), "r"(a[2]), "r"(a[3]), "r"(b0), "r"(b1));
}

// ---------------- conversion kernels -----------------------------------------
__global__ void k_split(const float* __restrict__ src, int n4, int sel) {
    __nv_bfloat16 *hi, *lo;
    if (sel == 0)      { hi = g_xhi; lo = g_xlo; }
    else if (sel == 1) { hi = g_whi; lo = g_wlo; }
    else               { hi = g_ahi; lo = g_alo; }
    int i = blockIdx.x * blockDim.x + threadIdx.x;
    if (i >= n4) return;
    float4 v = reinterpret_cast<const float4*>(src)[i];
    float a0 = v.x, a1 = v.y, a2 = v.z, a3 = v.w;
    __nv_bfloat16 h0 = __float2bfloat16(a0), h1 = __float2bfloat16(a1);
    __nv_bfloat16 h2 = __float2bfloat16(a2), h3 = __float2bfloat16(a3);
    __nv_bfloat16 l0 = __float2bfloat16(a0 - __bfloat162float(h0));
    __nv_bfloat16 l1 = __float2bfloat16(a1 - __bfloat162float(h1));
    __nv_bfloat16 l2 = __float2bfloat16(a2 - __bfloat162float(h2));
    __nv_bfloat16 l3 = __float2bfloat16(a3 - __bfloat162float(h3));
    __nv_bfloat162 hp0(h0, h1), hp1(h2, h3), lp0(l0, l1), lp1(l2, l3);
    uint2 hv = make_uint2(*reinterpret_cast<uint32_t*>(&hp0), *reinterpret_cast<uint32_t*>(&hp1));
    uint2 lv = make_uint2(*reinterpret_cast<uint32_t*>(&lp0), *reinterpret_cast<uint32_t*>(&lp1));
    *reinterpret_cast<uint2*>(hi + (size_t)4 * i) = hv;
    *reinterpret_cast<uint2*>(lo + (size_t)4 * i) = lv;
}

__global__ void k_bcat(const float* __restrict__ Bsrc, int n) {
    int i = blockIdx.x * blockDim.x + threadIdx.x;
    if (i >= n) return;
    int o = i >> 7, j = i & 127, e = j >> 4, r = j & 15;
    float v = Bsrc[((size_t)e * O_ + o) * R_ + r];
    __nv_bfloat16 h = __float2bfloat16(v);
    g_bchi[i] = h;
    g_bclo[i] = __float2bfloat16(v - __bfloat162float(h));
}

// ---------------- router ------------------------------------------------------
static constexpr int R_GS = 2052;
static constexpr int R_SMEM = (8 * R_GS + 128) * 4;

__global__ void __launch_bounds__(128) k_router(const float* __restrict__ x,
                                                const float* __restrict__ gw) {
    extern __shared__ char smraw[];
    float* sg = reinterpret_cast<float*>(smraw);
    float* lsm = sg + 8 * R_GS;
    for (int i = threadIdx.x; i < E_ * H_; i += 128) {
        int e = i >> 11, h = i & 2047;
        sg[e * R_GS + h] = gw[i];
    }
    __syncthreads();
    int tok = threadIdx.x >> 3, e = threadIdx.x & 7;
    int tG = blockIdx.x * 16 + tok;
    const float4* xr = reinterpret_cast<const float4*>(x + (size_t)tG * H_);
    const float* ge = sg + e * R_GS;
    float s0 = 0.f, s1 = 0.f, s2 = 0.f, s3 = 0.f;
#pragma unroll 4
    for (int h4 = 0; h4 < H_ / 4; h4++) {
        float4 xv = xr[h4];
        s0 += xv.x * ge[h4 * 4 + 0];
        s1 += xv.y * ge[h4 * 4 + 1];
        s2 += xv.z * ge[h4 * 4 + 2];
        s3 += xv.w * ge[h4 * 4 + 3];
    }
    lsm[tok * 8 + e] = (s0 + s1) + (s2 + s3);
    __syncthreads();
    if (threadIdx.x < 16) {
        int t = threadIdx.x;
        float l[8], m = -1e30f;
#pragma unroll
        for (int i = 0; i < 8; i++) { l[i] = lsm[t * 8 + i]; m = fmaxf(m, l[i]); }
        float p[8], sum = 0.f;
#pragma unroll
        for (int i = 0; i < 8; i++) { p[i] = expf(l[i] - m); sum += p[i]; }
#pragma unroll
        for (int i = 0; i < 8; i++) p[i] /= sum;
        int i1 = 0;
#pragma unroll
        for (int i = 1; i < 8; i++) if (p[i] > p[i1]) i1 = i;
        int i2 = (i1 == 0) ? 1 : 0;
#pragma unroll
        for (int i = 0; i < 8; i++) if (i != i1 && p[i] > p[i2]) i2 = i;
        float ws = p[i1] + p[i2];
        int tg = blockIdx.x * 16 + t;
#pragma unroll
        for (int i = 0; i < 8; i++) {
            float v = (i == i1) ? ALPHA_ * p[i1] / ws
                    : (i == i2) ? ALPHA_ * p[i2] / ws : 0.f;
            g_wmat[tg * 8 + i] = v;
        }
    }
}

// ---------------- GEMM engine: 4 warps, 64x64 warp tiles, 5-stage ------------
// CTA tile 128x128, BK=32. smem tile: 128 rows x 80B pitch (conflict-free).
static constexpr int PITCH_B = 80;
static constexpr int TILE_B  = 128 * PITCH_B;      // 10240
static constexpr int STAGE_B = 2 * TILE_B;         // 20480
static constexpr int NSTAGE  = 5;
static constexpr int G_SMEM  = NSTAGE * STAGE_B;   // 102400

// MODE 0: main GEMM out = x@W^T + hw@Bcat^T  (NKT = 204)
// MODE 1: h GEMM   h = x@Aall^T              (NKT = 192)
template <int MODE>
DI void tile_src(int kt, int m0, int n0,
                 const __nv_bfloat16*& As, const __nv_bfloat16*& Bs, int& ld) {
    if (MODE == 1) {
        int pl = kt >> 6, k0 = (kt & 63) * 32;
        As = (pl == 1 ? g_xlo : g_xhi) + (size_t)m0 * H_ + k0;
        Bs = (pl == 2 ? g_alo : g_ahi) + (size_t)n0 * H_ + k0;
        ld = H_;
    } else {
        if (kt < 192) {
            int pl = kt >> 6, k0 = (kt & 63) * 32;
            As = (pl == 1 ? g_xlo : g_xhi) + (size_t)m0 * H_ + k0;
            Bs = (pl == 2 ? g_wlo : g_whi) + (size_t)n0 * H_ + k0;
            ld = H_;
        } else {
            int q = kt - 192, pl = q >> 2, k0 = (q & 3) * 32;
            As = (pl == 1 ? g_hwlo : g_hwhi) + (size_t)m0 * ER_ + k0;
            Bs = (pl == 2 ? g_bclo : g_bchi) + (size_t)n0 * ER_ + k0;
            ld = ER_;
        }
    }
}

template <int MODE>
DI void load_tile(uint32_t sbase, int stage, int kt, int m0, int n0, int tid) {
    const __nv_bfloat16 *As, *Bs;
    int ld;
    tile_src<MODE>(kt, m0, n0, As, Bs, ld);
    uint32_t sa = sbase + stage * STAGE_B;
    uint32_t sbB = sa + TILE_B;
#pragma unroll
    for (int j = 0; j < 4; j++) {            // 512 16B-chunks per tile, 128 thr
        int c = tid + j * 128;
        int row = c >> 2, kc = c & 3;
        uint32_t off = (uint32_t)row * PITCH_B + (uint32_t)kc * 16;
        cpasync16(sa + off, As + (size_t)row * ld + kc * 8);
        cpasync16(sbB + off, Bs + (size_t)row * ld + kc * 8);
    }
    cp_commit();
}

DI void compute_stage(uint32_t sa, uint32_t sbB, float acc[4][8][4],
                      uint32_t aoff, uint32_t boff) {
#pragma unroll
    for (int ks = 0; ks < 2; ks++) {
        uint32_t af[4][4], bfr[4][4];
#pragma unroll
        for (int mt = 0; mt < 4; mt++)
            ldm_x4(af[mt], sa + aoff + mt * (16 * PITCH_B) + ks * 32);
#pragma unroll
        for (int p = 0; p < 4; p++)
            ldm_x4(bfr[p], sbB + boff + p * (16 * PITCH_B) + ks * 32);
#pragma unroll
        for (int mt = 0; mt < 4; mt++)
#pragma unroll
            for (int nt = 0; nt < 8; nt++)
                mma_bf16(acc[mt][nt], af[mt],
                         bfr[nt >> 1][(nt & 1) * 2], bfr[nt >> 1][(nt & 1) * 2 + 1]);
    }
}

template <int MODE>
__global__ void __launch_bounds__(128, 2) k_gemm(float* __restrict__ out) {
    extern __shared__ __align__(128) char smem[];
    uint32_t sbase = smem_u32(smem);
    int tid = threadIdx.x, lane = tid & 31, w = tid >> 5;
    int warp_m = w >> 1, warp_n = w & 1;   // 2x2 warp grid, 64x64 tiles

    int m0, n0, NKT;
    if (MODE == 0) { m0 = (blockIdx.x & 63) * 128; n0 = (blockIdx.x >> 6) * 128; NKT = 204; }
    else           { m0 = blockIdx.x * 128;        n0 = 0;                       NKT = 192; }

    float acc[4][8][4];
#pragma unroll
    for (int a = 0; a < 4; a++)
#pragma unroll
        for (int b = 0; b < 8; b++)
#pragma unroll
            for (int c = 0; c < 4; c++) acc[a][b][c] = 0.f;

    uint32_t aoff = (uint32_t)(warp_m * 64 + (lane & 7) + ((lane >> 3) & 1) * 8) * PITCH_B
                  + (uint32_t)(lane >> 4) * 16;
    uint32_t boff = (uint32_t)(warp_n * 64 + (lane & 7) + ((lane >> 4) & 1) * 8) * PITCH_B
                  + (uint32_t)((lane >> 3) & 1) * 16;

    // prologue: stages 0..3
#pragma unroll
    for (int s = 0; s < NSTAGE - 1; s++)
        load_tile<MODE>(sbase, s, s, m0, n0, tid);

    int stage = 0;
    for (int kt = 0; kt < NKT; kt++) {
        cp_wait<NSTAGE - 2>();       // stage kt resident
        __syncthreads();             // prev iter's reads of (kt+4)%5 done
        if (kt + NSTAGE - 1 < NKT) {
            int s2 = stage + NSTAGE - 1; if (s2 >= NSTAGE) s2 -= NSTAGE;
            load_tile<MODE>(sbase, s2, kt + NSTAGE - 1, m0, n0, tid);
        } else {
            cp_commit();             // keep group accounting uniform
        }
        uint32_t sa = sbase + stage * STAGE_B;
        compute_stage(sa, sa + TILE_B, acc, aoff, boff);
        if (++stage == NSTAGE) stage = 0;
    }

    if (MODE == 0) {
#pragma unroll
        for (int mt = 0; mt < 4; mt++) {
            int r0 = m0 + warp_m * 64 + mt * 16 + (lane >> 2);
#pragma unroll
            for (int nt = 0; nt < 8; nt++) {
                int col = n0 + warp_n * 64 + nt * 8 + (lane & 3) * 2;
                float2 v01 = make_float2(acc[mt][nt][0], acc[mt][nt][1]);
                float2 v23 = make_float2(acc[mt][nt][2], acc[mt][nt][3]);
                *reinterpret_cast<float2*>(out + (size_t)r0 * O_ + col) = v01;
                *reinterpret_cast<float2*>(out + (size_t)(r0 + 8) * O_ + col) = v23;
            }
        }
    } else {
#pragma unroll
        for (int mt = 0; mt < 4; mt++) {
            int t0 = m0 + warp_m * 64 + mt * 16 + (lane >> 2);
#pragma unroll
            for (int nt = 0; nt < 8; nt++) {
                int j = warp_n * 64 + nt * 8 + (lane & 3) * 2;
#pragma unroll
                for (int half = 0; half < 2; half++) {
                    int t = t0 + half * 8;
                    float wm = g_wmat[t * 8 + (j >> 4)];
                    float h0 = acc[mt][nt][half * 2 + 0] * wm;
                    float h1 = acc[mt][nt][half * 2 + 1] * wm;
                    __nv_bfloat16 b0 = __float2bfloat16(h0);
                    __nv_bfloat16 b1 = __float2bfloat16(h1);
                    __nv_bfloat16 c0 = __float2bfloat16(h0 - __bfloat162float(b0));
                    __nv_bfloat16 c1 = __float2bfloat16(h1 - __bfloat162float(b1));
                    __nv_bfloat162 hp(b0, b1), lp(c0, c1);
                    *reinterpret_cast<uint32_t*>(g_hwhi + (size_t)t * ER_ + j) =
                        *reinterpret_cast<uint32_t*>(&hp);
                    *reinterpret_cast<uint32_t*>(g_hwlo + (size_t)t * ER_ + j) =
                        *reinterpret_cast<uint32_t*>(&lp);
                }
            }
        }
    }
}

// ---------------- launch ------------------------------------------------------
extern "C" void kernel_launch(void* const* d_in, const int* in_sizes, int n_in,
                              void* d_out, int out_size) {
    const float* x  = (const float*)d_in[0];   // [4,2048,2048]
    const float* W  = (const float*)d_in[1];   // [2048,2048]
    const float* gw = (const float*)d_in[2];   // [8,2048]
    const float* A  = (const float*)d_in[3];   // [8,16,2048]
    const float* B  = (const float*)d_in[4];   // [8,2048,16]
    float* out = (float*)d_out;

    cudaFuncSetAttribute(k_router,  cudaFuncAttributeMaxDynamicSharedMemorySize, R_SMEM);
    cudaFuncSetAttribute(k_gemm<0>, cudaFuncAttributeMaxDynamicSharedMemorySize, G_SMEM);
    cudaFuncSetAttribute(k_gemm<1>, cudaFuncAttributeMaxDynamicSharedMemorySize, G_SMEM);

    {
        int n4 = (T_ * H_) / 4;
        k_split<<<(n4 + 255) / 256, 256>>>(x, n4, 0);
        n4 = (O_ * H_) / 4;
        k_split<<<(n4 + 255) / 256, 256>>>(W, n4, 1);
        n4 = (ER_ * H_) / 4;
        k_split<<<(n4 + 255) / 256, 256>>>(A, n4, 2);
        int n = O_ * ER_;
        k_bcat<<<(n + 255) / 256, 256>>>(B, n);
    }
    k_router<<<T_ / 16, 128, R_SMEM>>>(x, gw);
    k_gemm<1><<<T_ / 128, 128, G_SMEM>>>(nullptr);
    k_gemm<0><<<(T_ / 128) * (O_ / 128), 128, G_SMEM>>>(out);
}

// round 6
// speedup vs baseline: 2.5022x; 1.2645x over previous
#include <cuda_runtime.h>
#include <cuda_bf16.h>
#include <cuda_fp16.h>
#include <cstdint>
#include <math.h>

#define DI __device__ __forceinline__

static constexpr int T_  = 8192;
static constexpr int H_  = 2048;
static constexpr int O_  = 2048;
static constexpr int E_  = 8;
static constexpr int R_  = 16;
static constexpr int ER_ = 128;
static constexpr float ALPHA_ = 16.0f;

// ---------------- scratch (__device__ globals) ------------------------------
__device__ __align__(256) __half         g_xh [T_ * H_];   // fp16 x (main GEMM)
__device__ __align__(256) __nv_bfloat16  g_xhi[T_ * H_];   // bf16 planes (h-GEMM)
__device__ __align__(256) __nv_bfloat16  g_xlo[T_ * H_];
__device__ __align__(256) __half         g_wh [O_ * H_];   // fp16 W
__device__ __align__(256) __nv_bfloat16  g_ahi[ER_ * H_];
__device__ __align__(256) __nv_bfloat16  g_alo[ER_ * H_];
__device__ __align__(256) __nv_bfloat16  g_bchi[O_ * ER_];
__device__ __align__(256) __nv_bfloat16  g_bclo[O_ * ER_];
__device__ __align__(256) __nv_bfloat16  g_hwhi[T_ * ER_];
__device__ __align__(256) __nv_bfloat16  g_hwlo[T_ * ER_];
__device__ __align__(256) float          g_wmat[T_ * E_];

// ---------------- PTX helpers (base-ISA only) --------------------------------
DI uint32_t smem_u32(const void* p) {
    uint32_t a;
    asm("{ .reg .u64 t; cvta.to.shared.u64 t, %1; cvt.u32.u64 %0, t; }"
        : "=r"(a) : "l"(p));
    return a;
}
DI void cpasync16(uint32_t dst, const void* src) {
    asm volatile("cp.async.cg.shared.global [%0], [%1], 16;" :: "r"(dst), "l"(src));
}
DI void cp_commit() { asm volatile("cp.async.commit_group;" ::: "memory"); }
template <int N> DI void cp_wait() {
    asm volatile("cp.async.wait_group %0;" :: "n"(N) : "memory");
}
DI void ldm_x4(uint32_t* r, uint32_t a) {
    asm volatile("ldmatrix.sync.aligned.m8n8.x4.shared.b16 {%0,%1,%2,%3}, [%4];"
                 : "=r"(r[0]), "=r"(r[1]), "=r"(r[2]), "=r"(r[3]) : "r"(a));
}
DI void mma_bf16(float* c, const uint32_t* a, uint32_t b0, uint32_t b1) {
    asm volatile(
        "mma.sync.aligned.m16n8k16.row.col.f32.bf16.bf16.f32 "
        "{%0,%1,%2,%3}, {%4,%5,%6,%7}, {%8,%9}, {%0,%1,%2,%3};"
        : "+f"(c[0]), "+f"(c[1]), "+f"(c[2]), "+f"(c[3])
        : "r"(a[0]), "r"(a[1]), "r"(a[2]), "r"(a[3]), "r"(b0), "r"(b1));
}
DI void mma_f16(float* c, const uint32_t* a, uint32_t b0, uint32_t b1) {
    asm volatile(
        "mma.sync.aligned.m16n8k16.row.col.f32.f16.f16.f32 "
        "{%0,%1,%2,%3}, {%4,%5,%6,%7}, {%8,%9}, {%0,%1,%2,%3};"
        : "+f"(c[0]), "+f"(c[1]), "+f"(c[2]), "+f"(c[3])
        : "r"(a[0]), "r"(a[1]), "r"(a[2]), "r"(a[3]), "r"(b0), "r"(b1));
}

// ---------------- prep kernels ------------------------------------------------
// x: fp16 plane + bf16 hi/lo planes
__global__ void k_prep_x(const float* __restrict__ src, int n4) {
    int i = blockIdx.x * blockDim.x + threadIdx.x;
    if (i >= n4) return;
    float4 v = reinterpret_cast<const float4*>(src)[i];
    float a0 = v.x, a1 = v.y, a2 = v.z, a3 = v.w;
    __half2 f0(__float2half_rn(a0), __float2half_rn(a1));
    __half2 f1(__float2half_rn(a2), __float2half_rn(a3));
    uint2 fv = make_uint2(*reinterpret_cast<uint32_t*>(&f0), *reinterpret_cast<uint32_t*>(&f1));
    *reinterpret_cast<uint2*>(g_xh + (size_t)4 * i) = fv;
    __nv_bfloat16 h0 = __float2bfloat16(a0), h1 = __float2bfloat16(a1);
    __nv_bfloat16 h2 = __float2bfloat16(a2), h3 = __float2bfloat16(a3);
    __nv_bfloat16 l0 = __float2bfloat16(a0 - __bfloat162float(h0));
    __nv_bfloat16 l1 = __float2bfloat16(a1 - __bfloat162float(h1));
    __nv_bfloat16 l2 = __float2bfloat16(a2 - __bfloat162float(h2));
    __nv_bfloat16 l3 = __float2bfloat16(a3 - __bfloat162float(h3));
    __nv_bfloat162 hp0(h0, h1), hp1(h2, h3), lp0(l0, l1), lp1(l2, l3);
    uint2 hv = make_uint2(*reinterpret_cast<uint32_t*>(&hp0), *reinterpret_cast<uint32_t*>(&hp1));
    uint2 lv = make_uint2(*reinterpret_cast<uint32_t*>(&lp0), *reinterpret_cast<uint32_t*>(&lp1));
    *reinterpret_cast<uint2*>(g_xhi + (size_t)4 * i) = hv;
    *reinterpret_cast<uint2*>(g_xlo + (size_t)4 * i) = lv;
}

// W: fp16 only
__global__ void k_prep_w(const float* __restrict__ src, int n4) {
    int i = blockIdx.x * blockDim.x + threadIdx.x;
    if (i >= n4) return;
    float4 v = reinterpret_cast<const float4*>(src)[i];
    __half2 f0(__float2half_rn(v.x), __float2half_rn(v.y));
    __half2 f1(__float2half_rn(v.z), __float2half_rn(v.w));
    uint2 fv = make_uint2(*reinterpret_cast<uint32_t*>(&f0), *reinterpret_cast<uint32_t*>(&f1));
    *reinterpret_cast<uint2*>(g_wh + (size_t)4 * i) = fv;
}

// A: bf16 hi/lo
__global__ void k_prep_a(const float* __restrict__ src, int n4) {
    int i = blockIdx.x * blockDim.x + threadIdx.x;
    if (i >= n4) return;
    float4 v = reinterpret_cast<const float4*>(src)[i];
    float a0 = v.x, a1 = v.y, a2 = v.z, a3 = v.w;
    __nv_bfloat16 h0 = __float2bfloat16(a0), h1 = __float2bfloat16(a1);
    __nv_bfloat16 h2 = __float2bfloat16(a2), h3 = __float2bfloat16(a3);
    __nv_bfloat16 l0 = __float2bfloat16(a0 - __bfloat162float(h0));
    __nv_bfloat16 l1 = __float2bfloat16(a1 - __bfloat162float(h1));
    __nv_bfloat16 l2 = __float2bfloat16(a2 - __bfloat162float(h2));
    __nv_bfloat16 l3 = __float2bfloat16(a3 - __bfloat162float(h3));
    __nv_bfloat162 hp0(h0, h1), hp1(h2, h3), lp0(l0, l1), lp1(l2, l3);
    uint2 hv = make_uint2(*reinterpret_cast<uint32_t*>(&hp0), *reinterpret_cast<uint32_t*>(&hp1));
    uint2 lv = make_uint2(*reinterpret_cast<uint32_t*>(&lp0), *reinterpret_cast<uint32_t*>(&lp1));
    *reinterpret_cast<uint2*>(g_ahi + (size_t)4 * i) = hv;
    *reinterpret_cast<uint2*>(g_alo + (size_t)4 * i) = lv;
}

__global__ void k_bcat(const float* __restrict__ Bsrc, int n) {
    int i = blockIdx.x * blockDim.x + threadIdx.x;
    if (i >= n) return;
    int o = i >> 7, j = i & 127, e = j >> 4, r = j & 15;
    float v = Bsrc[((size_t)e * O_ + o) * R_ + r];
    __nv_bfloat16 h = __float2bfloat16(v);
    g_bchi[i] = h;
    g_bclo[i] = __float2bfloat16(v - __bfloat162float(h));
}

// ---------------- router ------------------------------------------------------
static constexpr int R_GS = 2052;
static constexpr int R_SMEM = (8 * R_GS + 128) * 4;

__global__ void __launch_bounds__(128) k_router(const float* __restrict__ x,
                                                const float* __restrict__ gw) {
    extern __shared__ char smraw[];
    float* sg = reinterpret_cast<float*>(smraw);
    float* lsm = sg + 8 * R_GS;
    for (int i = threadIdx.x; i < E_ * H_; i += 128) {
        int e = i >> 11, h = i & 2047;
        sg[e * R_GS + h] = gw[i];
    }
    __syncthreads();
    int tok = threadIdx.x >> 3, e = threadIdx.x & 7;
    int tG = blockIdx.x * 16 + tok;
    const float4* xr = reinterpret_cast<const float4*>(x + (size_t)tG * H_);
    const float* ge = sg + e * R_GS;
    float s0 = 0.f, s1 = 0.f, s2 = 0.f, s3 = 0.f;
#pragma unroll 4
    for (int h4 = 0; h4 < H_ / 4; h4++) {
        float4 xv = xr[h4];
        s0 += xv.x * ge[h4 * 4 + 0];
        s1 += xv.y * ge[h4 * 4 + 1];
        s2 += xv.z * ge[h4 * 4 + 2];
        s3 += xv.w * ge[h4 * 4 + 3];
    }
    lsm[tok * 8 + e] = (s0 + s1) + (s2 + s3);
    __syncthreads();
    if (threadIdx.x < 16) {
        int t = threadIdx.x;
        float l[8], m = -1e30f;
#pragma unroll
        for (int i = 0; i < 8; i++) { l[i] = lsm[t * 8 + i]; m = fmaxf(m, l[i]); }
        float p[8], sum = 0.f;
#pragma unroll
        for (int i = 0; i < 8; i++) { p[i] = expf(l[i] - m); sum += p[i]; }
#pragma unroll
        for (int i = 0; i < 8; i++) p[i] /= sum;
        int i1 = 0;
#pragma unroll
        for (int i = 1; i < 8; i++) if (p[i] > p[i1]) i1 = i;
        int i2 = (i1 == 0) ? 1 : 0;
#pragma unroll
        for (int i = 0; i < 8; i++) if (i != i1 && p[i] > p[i2]) i2 = i;
        float ws = p[i1] + p[i2];
        int tg = blockIdx.x * 16 + t;
#pragma unroll
        for (int i = 0; i < 8; i++) {
            float v = (i == i1) ? ALPHA_ * p[i1] / ws
                    : (i == i2) ? ALPHA_ * p[i2] / ws : 0.f;
            g_wmat[tg * 8 + i] = v;
        }
    }
}

// ---------------- GEMM engine -------------------------------------------------
// MODE 0: main GEMM, CTA tile 128x128, NKT=76 (64 fp16 base + 12 bf16 lora)
// MODE 1: h GEMM,    CTA tile  64x128, NKT=192 (bf16 3-pass), grid 128 CTAs
static constexpr int PITCH_B = 80;
static constexpr int NSTAGE  = 5;

template <int MODE> struct Cfg {
    static constexpr int BM     = (MODE == 0) ? 128 : 64;
    static constexpr int MT     = (MODE == 0) ? 4 : 2;      // 16-row frags per warp
    static constexpr int TILE_A = BM * PITCH_B;
    static constexpr int TILE_BB = 128 * PITCH_B;
    static constexpr int STAGE  = TILE_A + TILE_BB;
    static constexpr int SMEM   = NSTAGE * STAGE;
    static constexpr int NKT    = (MODE == 0) ? 76 : 192;
};

template <int MODE>
DI void tile_src(int kt, int m0, int n0,
                 const __nv_bfloat16*& As, const __nv_bfloat16*& Bs, int& ld) {
    if (MODE == 1) {
        int pl = kt >> 6, k0 = (kt & 63) * 32;
        As = (pl == 1 ? g_xlo : g_xhi) + (size_t)m0 * H_ + k0;
        Bs = (pl == 2 ? g_alo : g_ahi) + (size_t)n0 * H_ + k0;
        ld = H_;
    } else {
        if (kt < 64) {
            int k0 = kt * 32;
            As = reinterpret_cast<const __nv_bfloat16*>(g_xh) + (size_t)m0 * H_ + k0;
            Bs = reinterpret_cast<const __nv_bfloat16*>(g_wh) + (size_t)n0 * H_ + k0;
            ld = H_;
        } else {
            int q = kt - 64, pl = q >> 2, k0 = (q & 3) * 32;
            As = (pl == 1 ? g_hwlo : g_hwhi) + (size_t)m0 * ER_ + k0;
            Bs = (pl == 2 ? g_bclo : g_bchi) + (size_t)n0 * ER_ + k0;
            ld = ER_;
        }
    }
}

template <int MODE>
DI void load_tile(uint32_t sbase, int stage, int kt, int m0, int n0, int tid) {
    using C = Cfg<MODE>;
    const __nv_bfloat16 *As, *Bs;
    int ld;
    tile_src<MODE>(kt, m0, n0, As, Bs, ld);
    uint32_t sa = sbase + stage * C::STAGE;
    uint32_t sbB = sa + C::TILE_A;
#pragma unroll
    for (int j = 0; j < C::BM / 32; j++) {       // A: BM*4 chunks / 128 thr
        int c = tid + j * 128;
        int row = c >> 2, kc = c & 3;
        uint32_t off = (uint32_t)row * PITCH_B + (uint32_t)kc * 16;
        cpasync16(sa + off, As + (size_t)row * ld + kc * 8);
    }
#pragma unroll
    for (int j = 0; j < 4; j++) {                // B: 512 chunks
        int c = tid + j * 128;
        int row = c >> 2, kc = c & 3;
        uint32_t off = (uint32_t)row * PITCH_B + (uint32_t)kc * 16;
        cpasync16(sbB + off, Bs + (size_t)row * ld + kc * 8);
    }
    cp_commit();
}

template <int MT, bool BF>
DI void compute_stage(uint32_t sa, uint32_t sbB, float acc[MT][8][4],
                      uint32_t aoff, uint32_t boff) {
#pragma unroll
    for (int ks = 0; ks < 2; ks++) {
        uint32_t af[MT][4], bfr[4][4];
#pragma unroll
        for (int mt = 0; mt < MT; mt++)
            ldm_x4(af[mt], sa + aoff + mt * (16 * PITCH_B) + ks * 32);
#pragma unroll
        for (int p = 0; p < 4; p++)
            ldm_x4(bfr[p], sbB + boff + p * (16 * PITCH_B) + ks * 32);
#pragma unroll
        for (int mt = 0; mt < MT; mt++)
#pragma unroll
            for (int nt = 0; nt < 8; nt++) {
                uint32_t b0 = bfr[nt >> 1][(nt & 1) * 2], b1 = bfr[nt >> 1][(nt & 1) * 2 + 1];
                if (BF) mma_bf16(acc[mt][nt], af[mt], b0, b1);
                else    mma_f16 (acc[mt][nt], af[mt], b0, b1);
            }
    }
}

template <int MODE>
__global__ void __launch_bounds__(128, 2) k_gemm(float* __restrict__ out) {
    using C = Cfg<MODE>;
    extern __shared__ __align__(128) char smem[];
    uint32_t sbase = smem_u32(smem);
    int tid = threadIdx.x, lane = tid & 31, w = tid >> 5;
    int warp_m = w >> 1, warp_n = w & 1;

    int m0, n0;
    if (MODE == 0) { m0 = (blockIdx.x & 63) * 128; n0 = (blockIdx.x >> 6) * 128; }
    else           { m0 = blockIdx.x * 64;         n0 = 0; }

    float acc[C::MT][8][4];
#pragma unroll
    for (int a = 0; a < C::MT; a++)
#pragma unroll
        for (int b = 0; b < 8; b++)
#pragma unroll
            for (int c = 0; c < 4; c++) acc[a][b][c] = 0.f;

    uint32_t aoff = (uint32_t)(warp_m * (C::MT * 16) + (lane & 7) + ((lane >> 3) & 1) * 8) * PITCH_B
                  + (uint32_t)(lane >> 4) * 16;
    uint32_t boff = (uint32_t)(warp_n * 64 + (lane & 7) + ((lane >> 4) & 1) * 8) * PITCH_B
                  + (uint32_t)((lane >> 3) & 1) * 16;

#pragma unroll
    for (int s = 0; s < NSTAGE - 1; s++)
        load_tile<MODE>(sbase, s, s, m0, n0, tid);

    int stage = 0;
    for (int kt = 0; kt < C::NKT; kt++) {
        cp_wait<NSTAGE - 2>();
        __syncthreads();
        if (kt + NSTAGE - 1 < C::NKT) {
            int s2 = stage + NSTAGE - 1; if (s2 >= NSTAGE) s2 -= NSTAGE;
            load_tile<MODE>(sbase, s2, kt + NSTAGE - 1, m0, n0, tid);
        } else {
            cp_commit();
        }
        uint32_t sa = sbase + stage * C::STAGE;
        if (MODE == 0 && kt < 64)
            compute_stage<C::MT, false>(sa, sa + C::TILE_A, acc, aoff, boff);
        else
            compute_stage<C::MT, true>(sa, sa + C::TILE_A, acc, aoff, boff);
        if (++stage == NSTAGE) stage = 0;
    }

    if (MODE == 0) {
#pragma unroll
        for (int mt = 0; mt < C::MT; mt++) {
            int r0 = m0 + warp_m * 64 + mt * 16 + (lane >> 2);
#pragma unroll
            for (int nt = 0; nt < 8; nt++) {
                int col = n0 + warp_n * 64 + nt * 8 + (lane & 3) * 2;
                float2 v01 = make_float2(acc[mt][nt][0], acc[mt][nt][1]);
                float2 v23 = make_float2(acc[mt][nt][2], acc[mt][nt][3]);
                *reinterpret_cast<float2*>(out + (size_t)r0 * O_ + col) = v01;
                *reinterpret_cast<float2*>(out + (size_t)(r0 + 8) * O_ + col) = v23;
            }
        }
    } else {
#pragma unroll
        for (int mt = 0; mt < C::MT; mt++) {
            int t0 = m0 + warp_m * 32 + mt * 16 + (lane >> 2);
#pragma unroll
            for (int nt = 0; nt < 8; nt++) {
                int j = warp_n * 64 + nt * 8 + (lane & 3) * 2;
#pragma unroll
                for (int half = 0; half < 2; half++) {
                    int t = t0 + half * 8;
                    float wm = g_wmat[t * 8 + (j >> 4)];
                    float h0 = acc[mt][nt][half * 2 + 0] * wm;
                    float h1 = acc[mt][nt][half * 2 + 1] * wm;
                    __nv_bfloat16 b0 = __float2bfloat16(h0);
                    __nv_bfloat16 b1 = __float2bfloat16(h1);
                    __nv_bfloat16 c0 = __float2bfloat16(h0 - __bfloat162float(b0));
                    __nv_bfloat16 c1 = __float2bfloat16(h1 - __bfloat162float(b1));
                    __nv_bfloat162 hp(b0, b1), lp(c0, c1);
                    *reinterpret_cast<uint32_t*>(g_hwhi + (size_t)t * ER_ + j) =
                        *reinterpret_cast<uint32_t*>(&hp);
                    *reinterpret_cast<uint32_t*>(g_hwlo + (size_t)t * ER_ + j) =
                        *reinterpret_cast<uint32_t*>(&lp);
                }
            }
        }
    }
}

// ---------------- launch ------------------------------------------------------
extern "C" void kernel_launch(void* const* d_in, const int* in_sizes, int n_in,
                              void* d_out, int out_size) {
    const float* x  = (const float*)d_in[0];
    const float* W  = (const float*)d_in[1];
    const float* gw = (const float*)d_in[2];
    const float* A  = (const float*)d_in[3];
    const float* B  = (const float*)d_in[4];
    float* out = (float*)d_out;

    cudaFuncSetAttribute(k_router,  cudaFuncAttributeMaxDynamicSharedMemorySize, R_SMEM);
    cudaFuncSetAttribute(k_gemm<0>, cudaFuncAttributeMaxDynamicSharedMemorySize, Cfg<0>::SMEM);
    cudaFuncSetAttribute(k_gemm<1>, cudaFuncAttributeMaxDynamicSharedMemorySize, Cfg<1>::SMEM);

    int n4 = (T_ * H_) / 4;
    k_prep_x<<<(n4 + 255) / 256, 256>>>(x, n4);
    n4 = (O_ * H_) / 4;
    k_prep_w<<<(n4 + 255) / 256, 256>>>(W, n4);
    n4 = (ER_ * H_) / 4;
    k_prep_a<<<(n4 + 255) / 256, 256>>>(A, n4);
    int n = O_ * ER_;
    k_bcat<<<(n + 255) / 256, 256>>>(B, n);

    k_router<<<T_ / 16, 128, R_SMEM>>>(x, gw);
    k_gemm<1><<<T_ / 64, 128, Cfg<1>::SMEM>>>(nullptr);
    k_gemm<0><<<(T_ / 128) * (O_ / 128), 128, Cfg<0>::SMEM>>>(out);
}

// round 7
// speedup vs baseline: 4.4868x; 1.7932x over previous
#include <cuda_runtime.h>
#include <cuda_bf16.h>
#include <cuda_fp16.h>
#include <cstdint>
#include <math.h>

#define DI __device__ __forceinline__

static constexpr int T_  = 8192;
static constexpr int H_  = 2048;
static constexpr int O_  = 2048;
static constexpr int E_  = 8;
static constexpr int R_  = 16;
static constexpr int ER_ = 128;
static constexpr float ALPHA_ = 16.0f;

// ---------------- scratch (__device__ globals) ------------------------------
__device__ __align__(256) __half g_xh [T_ * H_];    // fp16 x
__device__ __align__(256) __half g_wh [O_ * H_];    // fp16 W
__device__ __align__(256) __half g_ah [ER_ * H_];   // fp16 stacked A
__device__ __align__(256) __half g_bch[O_ * ER_];   // fp16 Bcat[o, e*16+r]
__device__ __align__(256) __half g_hw [T_ * ER_];   // fp16 scaled h
__device__ __align__(256) float  g_wmat[T_ * E_];

// ---------------- PTX helpers (base-ISA only) --------------------------------
DI uint32_t smem_u32(const void* p) {
    uint32_t a;
    asm("{ .reg .u64 t; cvta.to.shared.u64 t, %1; cvt.u32.u64 %0, t; }"
        : "=r"(a) : "l"(p));
    return a;
}
DI void cpasync16(uint32_t dst, const void* src) {
    asm volatile("cp.async.cg.shared.global [%0], [%1], 16;" :: "r"(dst), "l"(src));
}
DI void cp_commit() { asm volatile("cp.async.commit_group;" ::: "memory"); }
template <int N> DI void cp_wait() {
    asm volatile("cp.async.wait_group %0;" :: "n"(N) : "memory");
}
DI void ldm_x4(uint32_t* r, uint32_t a) {
    asm volatile("ldmatrix.sync.aligned.m8n8.x4.shared.b16 {%0,%1,%2,%3}, [%4];"
                 : "=r"(r[0]), "=r"(r[1]), "=r"(r[2]), "=r"(r[3]) : "r"(a));
}
DI void mma_f16(float* c, const uint32_t* a, uint32_t b0, uint32_t b1) {
    asm volatile(
        "mma.sync.aligned.m16n8k16.row.col.f32.f16.f16.f32 "
        "{%0,%1,%2,%3}, {%4,%5,%6,%7}, {%8,%9}, {%0,%1,%2,%3};"
        : "+f"(c[0]), "+f"(c[1]), "+f"(c[2]), "+f"(c[3])
        : "r"(a[0]), "r"(a[1]), "r"(a[2]), "r"(a[3]), "r"(b0), "r"(b1));
}

DI void st_half4(__half* dst, float4 v) {
    __half2 f0(__float2half_rn(v.x), __float2half_rn(v.y));
    __half2 f1(__float2half_rn(v.z), __float2half_rn(v.w));
    uint2 u = make_uint2(*reinterpret_cast<uint32_t*>(&f0),
                         *reinterpret_cast<uint32_t*>(&f1));
    *reinterpret_cast<uint2*>(dst) = u;
}

// ---------------- merged prep kernel -----------------------------------------
// one grid covers: x->fp16, W->fp16, A->fp16, B->Bcat fp16 (all vec4)
static constexpr int PN_X = T_ * H_ / 4;
static constexpr int PN_W = O_ * H_ / 4;
static constexpr int PN_A = ER_ * H_ / 4;
static constexpr int PN_B = O_ * ER_ / 4;
static constexpr int PN_TOT = PN_X + PN_W + PN_A + PN_B;

__global__ void __launch_bounds__(256) k_prep(const float* __restrict__ x,
                                              const float* __restrict__ W,
                                              const float* __restrict__ A,
                                              const float* __restrict__ Bsrc) {
    int i = blockIdx.x * blockDim.x + threadIdx.x;
    if (i < PN_X) {
        st_half4(g_xh + (size_t)4 * i, reinterpret_cast<const float4*>(x)[i]);
    } else if (i < PN_X + PN_W) {
        int j = i - PN_X;
        st_half4(g_wh + (size_t)4 * j, reinterpret_cast<const float4*>(W)[j]);
    } else if (i < PN_X + PN_W + PN_A) {
        int j = i - (PN_X + PN_W);
        st_half4(g_ah + (size_t)4 * j, reinterpret_cast<const float4*>(A)[j]);
    } else if (i < PN_TOT) {
        int j = i - (PN_X + PN_W + PN_A);
        int o = j >> 5, c4 = (j & 31) * 4;         // col in [0,128)
        int e = c4 >> 4, r = c4 & 15;              // r..r+3 within one expert
        const float* bp = Bsrc + ((size_t)e * O_ + o) * R_ + r;
        float4 v = make_float4(bp[0], bp[1], bp[2], bp[3]);
        st_half4(g_bch + (size_t)o * ER_ + c4, v);
    }
}

// ---------------- router ------------------------------------------------------
static constexpr int R_GS = 2052;
static constexpr int R_SMEM = (8 * R_GS + 128) * 4;

__global__ void __launch_bounds__(128) k_router(const float* __restrict__ x,
                                                const float* __restrict__ gw) {
    extern __shared__ char smraw[];
    float* sg = reinterpret_cast<float*>(smraw);
    float* lsm = sg + 8 * R_GS;
    for (int i = threadIdx.x; i < E_ * H_; i += 128) {
        int e = i >> 11, h = i & 2047;
        sg[e * R_GS + h] = gw[i];
    }
    __syncthreads();
    int tok = threadIdx.x >> 3, e = threadIdx.x & 7;
    int tG = blockIdx.x * 16 + tok;
    const float4* xr = reinterpret_cast<const float4*>(x + (size_t)tG * H_);
    const float* ge = sg + e * R_GS;
    float s0 = 0.f, s1 = 0.f, s2 = 0.f, s3 = 0.f;
#pragma unroll 4
    for (int h4 = 0; h4 < H_ / 4; h4++) {
        float4 xv = xr[h4];
        s0 += xv.x * ge[h4 * 4 + 0];
        s1 += xv.y * ge[h4 * 4 + 1];
        s2 += xv.z * ge[h4 * 4 + 2];
        s3 += xv.w * ge[h4 * 4 + 3];
    }
    lsm[tok * 8 + e] = (s0 + s1) + (s2 + s3);
    __syncthreads();
    if (threadIdx.x < 16) {
        int t = threadIdx.x;
        float l[8], m = -1e30f;
#pragma unroll
        for (int i = 0; i < 8; i++) { l[i] = lsm[t * 8 + i]; m = fmaxf(m, l[i]); }
        float p[8], sum = 0.f;
#pragma unroll
        for (int i = 0; i < 8; i++) { p[i] = expf(l[i] - m); sum += p[i]; }
#pragma unroll
        for (int i = 0; i < 8; i++) p[i] /= sum;
        int i1 = 0;
#pragma unroll
        for (int i = 1; i < 8; i++) if (p[i] > p[i1]) i1 = i;
        int i2 = (i1 == 0) ? 1 : 0;
#pragma unroll
        for (int i = 0; i < 8; i++) if (i != i1 && p[i] > p[i2]) i2 = i;
        float ws = p[i1] + p[i2];
        int tg = blockIdx.x * 16 + t;
#pragma unroll
        for (int i = 0; i < 8; i++) {
            float v = (i == i1) ? ALPHA_ * p[i1] / ws
                    : (i == i2) ? ALPHA_ * p[i2] / ws : 0.f;
            g_wmat[tg * 8 + i] = v;
        }
    }
}

// ---------------- GEMM engine (all fp16, 5-stage, 1 sync/K-tile) --------------
// MODE 0: main GEMM, CTA 128x128, NKT=68 (64 base + 4 lora)
// MODE 1: h GEMM,    CTA  64x128, NKT=64, grid 128
static constexpr int PITCH_B = 80;
static constexpr int NSTAGE  = 5;

template <int MODE> struct Cfg {
    static constexpr int BM      = (MODE == 0) ? 128 : 64;
    static constexpr int MT      = (MODE == 0) ? 4 : 2;
    static constexpr int TILE_A  = BM * PITCH_B;
    static constexpr int TILE_BB = 128 * PITCH_B;
    static constexpr int STAGE   = TILE_A + TILE_BB;
    static constexpr int SMEM    = NSTAGE * STAGE;
    static constexpr int NKT     = (MODE == 0) ? 68 : 64;
};

template <int MODE>
DI void tile_src(int kt, int m0, int n0,
                 const __half*& As, const __half*& Bs, int& ld) {
    if (MODE == 1) {
        int k0 = kt * 32;
        As = g_xh + (size_t)m0 * H_ + k0;
        Bs = g_ah + k0;
        ld = H_;
    } else {
        if (kt < 64) {
            int k0 = kt * 32;
            As = g_xh + (size_t)m0 * H_ + k0;
            Bs = g_wh + (size_t)n0 * H_ + k0;
            ld = H_;
        } else {
            int k0 = (kt - 64) * 32;
            As = g_hw + (size_t)m0 * ER_ + k0;
            Bs = g_bch + (size_t)n0 * ER_ + k0;
            ld = ER_;
        }
    }
}

template <int MODE>
DI void load_tile(uint32_t sbase, int stage, int kt, int m0, int n0, int tid) {
    using C = Cfg<MODE>;
    const __half *As, *Bs;
    int ld;
    tile_src<MODE>(kt, m0, n0, As, Bs, ld);
    uint32_t sa = sbase + stage * C::STAGE;
    uint32_t sbB = sa + C::TILE_A;
#pragma unroll
    for (int j = 0; j < C::BM / 32; j++) {
        int c = tid + j * 128;
        int row = c >> 2, kc = c & 3;
        uint32_t off = (uint32_t)row * PITCH_B + (uint32_t)kc * 16;
        cpasync16(sa + off, As + (size_t)row * ld + kc * 8);
    }
#pragma unroll
    for (int j = 0; j < 4; j++) {
        int c = tid + j * 128;
        int row = c >> 2, kc = c & 3;
        uint32_t off = (uint32_t)row * PITCH_B + (uint32_t)kc * 16;
        cpasync16(sbB + off, Bs + (size_t)row * ld + kc * 8);
    }
    cp_commit();
}

template <int MT>
DI void compute_stage(uint32_t sa, uint32_t sbB, float acc[MT][8][4],
                      uint32_t aoff, uint32_t boff) {
#pragma unroll
    for (int ks = 0; ks < 2; ks++) {
        uint32_t af[MT][4], bfr[4][4];
#pragma unroll
        for (int mt = 0; mt < MT; mt++)
            ldm_x4(af[mt], sa + aoff + mt * (16 * PITCH_B) + ks * 32);
#pragma unroll
        for (int p = 0; p < 4; p++)
            ldm_x4(bfr[p], sbB + boff + p * (16 * PITCH_B) + ks * 32);
#pragma unroll
        for (int mt = 0; mt < MT; mt++)
#pragma unroll
            for (int nt = 0; nt < 8; nt++)
                mma_f16(acc[mt][nt], af[mt],
                        bfr[nt >> 1][(nt & 1) * 2], bfr[nt >> 1][(nt & 1) * 2 + 1]);
    }
}

template <int MODE>
__global__ void __launch_bounds__(128, 2) k_gemm(float* __restrict__ out) {
    using C = Cfg<MODE>;
    extern __shared__ __align__(128) char smem[];
    uint32_t sbase = smem_u32(smem);
    int tid = threadIdx.x, lane = tid & 31, w = tid >> 5;
    int warp_m = w >> 1, warp_n = w & 1;

    int m0, n0;
    if (MODE == 0) { m0 = (blockIdx.x & 63) * 128; n0 = (blockIdx.x >> 6) * 128; }
    else           { m0 = blockIdx.x * 64;         n0 = 0; }

    float acc[C::MT][8][4];
#pragma unroll
    for (int a = 0; a < C::MT; a++)
#pragma unroll
        for (int b = 0; b < 8; b++)
#pragma unroll
            for (int c = 0; c < 4; c++) acc[a][b][c] = 0.f;

    uint32_t aoff = (uint32_t)(warp_m * (C::MT * 16) + (lane & 7) + ((lane >> 3) & 1) * 8) * PITCH_B
                  + (uint32_t)(lane >> 4) * 16;
    uint32_t boff = (uint32_t)(warp_n * 64 + (lane & 7) + ((lane >> 4) & 1) * 8) * PITCH_B
                  + (uint32_t)((lane >> 3) & 1) * 16;

#pragma unroll
    for (int s = 0; s < NSTAGE - 1; s++)
        load_tile<MODE>(sbase, s, s, m0, n0, tid);

    int stage = 0;
    for (int kt = 0; kt < C::NKT; kt++) {
        cp_wait<NSTAGE - 2>();
        __syncthreads();
        if (kt + NSTAGE - 1 < C::NKT) {
            int s2 = stage + NSTAGE - 1; if (s2 >= NSTAGE) s2 -= NSTAGE;
            load_tile<MODE>(sbase, s2, kt + NSTAGE - 1, m0, n0, tid);
        } else {
            cp_commit();
        }
        uint32_t sa = sbase + stage * C::STAGE;
        compute_stage<C::MT>(sa, sa + C::TILE_A, acc, aoff, boff);
        if (++stage == NSTAGE) stage = 0;
    }

    if (MODE == 0) {
#pragma unroll
        for (int mt = 0; mt < C::MT; mt++) {
            int r0 = m0 + warp_m * 64 + mt * 16 + (lane >> 2);
#pragma unroll
            for (int nt = 0; nt < 8; nt++) {
                int col = n0 + warp_n * 64 + nt * 8 + (lane & 3) * 2;
                float2 v01 = make_float2(acc[mt][nt][0], acc[mt][nt][1]);
                float2 v23 = make_float2(acc[mt][nt][2], acc[mt][nt][3]);
                *reinterpret_cast<float2*>(out + (size_t)r0 * O_ + col) = v01;
                *reinterpret_cast<float2*>(out + (size_t)(r0 + 8) * O_ + col) = v23;
            }
        }
    } else {
        // scale by routing weight, store hw fp16
#pragma unroll
        for (int mt = 0; mt < C::MT; mt++) {
            int t0 = m0 + warp_m * 32 + mt * 16 + (lane >> 2);
#pragma unroll
            for (int nt = 0; nt < 8; nt++) {
                int j = warp_n * 64 + nt * 8 + (lane & 3) * 2;
#pragma unroll
                for (int half = 0; half < 2; half++) {
                    int t = t0 + half * 8;
                    float wm = g_wmat[t * 8 + (j >> 4)];
                    __half2 hv(__float2half_rn(acc[mt][nt][half * 2 + 0] * wm),
                               __float2half_rn(acc[mt][nt][half * 2 + 1] * wm));
                    *reinterpret_cast<uint32_t*>(g_hw + (size_t)t * ER_ + j) =
                        *reinterpret_cast<uint32_t*>(&hv);
                }
            }
        }
    }
}

// ---------------- launch ------------------------------------------------------
extern "C" void kernel_launch(void* const* d_in, const int* in_sizes, int n_in,
                              void* d_out, int out_size) {
    const float* x  = (const float*)d_in[0];
    const float* W  = (const float*)d_in[1];
    const float* gw = (const float*)d_in[2];
    const float* A  = (const float*)d_in[3];
    const float* B  = (const float*)d_in[4];
    float* out = (float*)d_out;

    cudaFuncSetAttribute(k_router,  cudaFuncAttributeMaxDynamicSharedMemorySize, R_SMEM);
    cudaFuncSetAttribute(k_gemm<0>, cudaFuncAttributeMaxDynamicSharedMemorySize, Cfg<0>::SMEM);
    cudaFuncSetAttribute(k_gemm<1>, cudaFuncAttributeMaxDynamicSharedMemorySize, Cfg<1>::SMEM);

    k_prep<<<(PN_TOT + 255) / 256, 256>>>(x, W, A, B);
    k_router<<<T_ / 16, 128, R_SMEM>>>(x, gw);
    k_gemm<1><<<T_ / 64, 128, Cfg<1>::SMEM>>>(nullptr);
    k_gemm<0><<<(T_ / 128) * (O_ / 128), 128, Cfg<0>::SMEM>>>(out);
}

// round 9
// speedup vs baseline: 4.5592x; 1.0161x over previous
#include <cuda_runtime.h>
#include <cuda_bf16.h>
#include <cuda_fp16.h>
#include <cstdint>
#include <math.h>

#define DI __device__ __forceinline__

static constexpr int T_  = 8192;
static constexpr int H_  = 2048;
static constexpr int O_  = 2048;
static constexpr int E_  = 8;
static constexpr int R_  = 16;
static constexpr int ER_ = 128;
static constexpr float ALPHA_ = 16.0f;

// ---------------- scratch (__device__ globals) ------------------------------
__device__ __align__(256) __half g_xh [T_ * H_];    // fp16 x
__device__ __align__(256) __half g_wh [O_ * H_];    // fp16 W
__device__ __align__(256) __half g_ah [ER_ * H_];   // fp16 stacked A
__device__ __align__(256) __half g_bch[O_ * ER_];   // fp16 Bcat[o, e*16+r]
__device__ __align__(256) __half g_hw [T_ * ER_];   // fp16 scaled h
__device__ __align__(256) float  g_wmat[T_ * E_];

// ---------------- PTX helpers (base-ISA only) --------------------------------
DI uint32_t smem_u32(const void* p) {
    uint32_t a;
    asm("{ .reg .u64 t; cvta.to.shared.u64 t, %1; cvt.u32.u64 %0, t; }"
        : "=r"(a) : "l"(p));
    return a;
}
DI void cpasync16(uint32_t dst, const void* src) {
    asm volatile("cp.async.cg.shared.global [%0], [%1], 16;" :: "r"(dst), "l"(src));
}
DI void cp_commit() { asm volatile("cp.async.commit_group;" ::: "memory"); }
template <int N> DI void cp_wait() {
    asm volatile("cp.async.wait_group %0;" :: "n"(N) : "memory");
}
DI void ldm_x4(uint32_t* r, uint32_t a) {
    asm volatile("ldmatrix.sync.aligned.m8n8.x4.shared.b16 {%0,%1,%2,%3}, [%4];"
                 : "=r"(r[0]), "=r"(r[1]), "=r"(r[2]), "=r"(r[3]) : "r"(a));
}
DI void mma_f16(float* c, const uint32_t* a, uint32_t b0, uint32_t b1) {
    asm volatile(
        "mma.sync.aligned.m16n8k16.row.col.f32.f16.f16.f32 "
        "{%0,%1,%2,%3}, {%4,%5,%6,%7}, {%8,%9}, {%0,%1,%2,%3};"
        : "+f"(c[0]), "+f"(c[1]), "+f"(c[2]), "+f"(c[3])
        : "r"(a[0]), "r"(a[1]), "r"(a[2]), "r"(a[3]), "r"(b0), "r"(b1));
}

DI void st_half4(__half* dst, float4 v) {
    __half2 f0(__float2half_rn(v.x), __float2half_rn(v.y));
    __half2 f1(__float2half_rn(v.z), __float2half_rn(v.w));
    uint2 u = make_uint2(*reinterpret_cast<uint32_t*>(&f0),
                         *reinterpret_cast<uint32_t*>(&f1));
    *reinterpret_cast<uint2*>(dst) = u;
}

// ---------------- merged prep kernel -----------------------------------------
static constexpr int PN_X = T_ * H_ / 4;
static constexpr int PN_W = O_ * H_ / 4;
static constexpr int PN_A = ER_ * H_ / 4;
static constexpr int PN_B = O_ * ER_ / 4;
static constexpr int PN_TOT = PN_X + PN_W + PN_A + PN_B;

__global__ void __launch_bounds__(256) k_prep(const float* __restrict__ x,
                                              const float* __restrict__ W,
                                              const float* __restrict__ A,
                                              const float* __restrict__ Bsrc) {
    int i = blockIdx.x * blockDim.x + threadIdx.x;
    if (i < PN_X) {
        st_half4(g_xh + (size_t)4 * i, reinterpret_cast<const float4*>(x)[i]);
    } else if (i < PN_X + PN_W) {
        int j = i - PN_X;
        st_half4(g_wh + (size_t)4 * j, reinterpret_cast<const float4*>(W)[j]);
    } else if (i < PN_X + PN_W + PN_A) {
        int j = i - (PN_X + PN_W);
        st_half4(g_ah + (size_t)4 * j, reinterpret_cast<const float4*>(A)[j]);
    } else if (i < PN_TOT) {
        int j = i - (PN_X + PN_W + PN_A);
        int o = j >> 5, c4 = (j & 31) * 4;
        int e = c4 >> 4, r = c4 & 15;
        const float* bp = Bsrc + ((size_t)e * O_ + o) * R_ + r;
        float4 v = make_float4(bp[0], bp[1], bp[2], bp[3]);
        st_half4(g_bch + (size_t)o * ER_ + c4, v);
    }
}

// ---------------- router ------------------------------------------------------
static constexpr int R_GS = 2052;
static constexpr int R_SMEM = (8 * R_GS + 128) * 4;

__global__ void __launch_bounds__(128) k_router(const float* __restrict__ x,
                                                const float* __restrict__ gw) {
    extern __shared__ char smraw[];
    float* sg = reinterpret_cast<float*>(smraw);
    float* lsm = sg + 8 * R_GS;
    for (int i = threadIdx.x; i < E_ * H_; i += 128) {
        int e = i >> 11, h = i & 2047;
        sg[e * R_GS + h] = gw[i];
    }
    __syncthreads();
    int tok = threadIdx.x >> 3, e = threadIdx.x & 7;
    int tG = blockIdx.x * 16 + tok;
    const float4* xr = reinterpret_cast<const float4*>(x + (size_t)tG * H_);
    const float* ge = sg + e * R_GS;
    float s0 = 0.f, s1 = 0.f, s2 = 0.f, s3 = 0.f;
#pragma unroll 4
    for (int h4 = 0; h4 < H_ / 4; h4++) {
        float4 xv = xr[h4];
        s0 += xv.x * ge[h4 * 4 + 0];
        s1 += xv.y * ge[h4 * 4 + 1];
        s2 += xv.z * ge[h4 * 4 + 2];
        s3 += xv.w * ge[h4 * 4 + 3];
    }
    lsm[tok * 8 + e] = (s0 + s1) + (s2 + s3);
    __syncthreads();
    if (threadIdx.x < 16) {
        int t = threadIdx.x;
        float l[8], m = -1e30f;
#pragma unroll
        for (int i = 0; i < 8; i++) { l[i] = lsm[t * 8 + i]; m = fmaxf(m, l[i]); }
        float p[8], sum = 0.f;
#pragma unroll
        for (int i = 0; i < 8; i++) { p[i] = expf(l[i] - m); sum += p[i]; }
#pragma unroll
        for (int i = 0; i < 8; i++) p[i] /= sum;
        int i1 = 0;
#pragma unroll
        for (int i = 1; i < 8; i++) if (p[i] > p[i1]) i1 = i;
        int i2 = (i1 == 0) ? 1 : 0;
#pragma unroll
        for (int i = 0; i < 8; i++) if (i != i1 && p[i] > p[i2]) i2 = i;
        float ws = p[i1] + p[i2];
        int tg = blockIdx.x * 16 + t;
#pragma unroll
        for (int i = 0; i < 8; i++) {
            float v = (i == i1) ? ALPHA_ * p[i1] / ws
                    : (i == i2) ? ALPHA_ * p[i2] / ws : 0.f;
            g_wmat[tg * 8 + i] = v;
        }
    }
}

// ---------------- GEMM engine: BK=64, 3 stages, frag double-buffer ------------
// pitch 144B (9 granules, gcd(9,8)=1): conflict-free cp.async stores + ldmatrix.
// MODE 0: main GEMM, CTA 128x128, NKT=34 (32 base + 2 lora)
// MODE 1: h GEMM,    CTA  64x128, NKT=32, grid 128
static constexpr int PITCH_B = 144;
static constexpr int NSTAGE  = 3;

template <int MODE> struct Cfg {
    static constexpr int BM      = (MODE == 0) ? 128 : 64;
    static constexpr int MT      = (MODE == 0) ? 4 : 2;
    static constexpr int TILE_A  = BM * PITCH_B;
    static constexpr int TILE_BB = 128 * PITCH_B;
    static constexpr int STAGE   = TILE_A + TILE_BB;
    static constexpr int SMEM    = NSTAGE * STAGE;
    static constexpr int NKT     = (MODE == 0) ? 34 : 32;
};

template <int MODE>
DI void tile_src(int kt, int m0, int n0,
                 const __half*& As, const __half*& Bs, int& ld) {
    if (MODE == 1) {
        int k0 = kt * 64;
        As = g_xh + (size_t)m0 * H_ + k0;
        Bs = g_ah + k0;
        ld = H_;
    } else {
        if (kt < 32) {
            int k0 = kt * 64;
            As = g_xh + (size_t)m0 * H_ + k0;
            Bs = g_wh + (size_t)n0 * H_ + k0;
            ld = H_;
        } else {
            int k0 = (kt - 32) * 64;
            As = g_hw + (size_t)m0 * ER_ + k0;
            Bs = g_bch + (size_t)n0 * ER_ + k0;
            ld = ER_;
        }
    }
}

template <int MODE>
DI void load_tile(uint32_t sbase, int stage, int kt, int m0, int n0, int tid) {
    using C = Cfg<MODE>;
    const __half *As, *Bs;
    int ld;
    tile_src<MODE>(kt, m0, n0, As, Bs, ld);
    uint32_t sa = sbase + stage * C::STAGE;
    uint32_t sbB = sa + C::TILE_A;
#pragma unroll
    for (int j = 0; j < C::BM / 16; j++) {       // A: BM rows x 8 chunks
        int c = tid + j * 128;
        int row = c >> 3, kc = c & 7;
        uint32_t off = (uint32_t)row * PITCH_B + (uint32_t)kc * 16;
        cpasync16(sa + off, As + (size_t)row * ld + kc * 8);
    }
#pragma unroll
    for (int j = 0; j < 8; j++) {                // B: 128 rows x 8 chunks
        int c = tid + j * 128;
        int row = c >> 3, kc = c & 7;
        uint32_t off = (uint32_t)row * PITCH_B + (uint32_t)kc * 16;
        cpasync16(sbB + off, Bs + (size_t)row * ld + kc * 8);
    }
    cp_commit();
}

template <int MT>
DI void load_frags(int ks, uint32_t sa, uint32_t sbB, uint32_t aoff, uint32_t boff,
                   uint32_t af[][4], uint32_t bfr[][4]) {
#pragma unroll
    for (int mt = 0; mt < MT; mt++)
        ldm_x4(af[mt], sa + aoff + mt * (16 * PITCH_B) + ks * 32);
#pragma unroll
    for (int p = 0; p < 4; p++)
        ldm_x4(bfr[p], sbB + boff + p * (16 * PITCH_B) + ks * 32);
}

template <int MT>
DI void compute_stage(uint32_t sa, uint32_t sbB, float acc[][8][4],
                      uint32_t aoff, uint32_t boff) {
    uint32_t af[2][MT][4], bfr[2][4][4];
    load_frags<MT>(0, sa, sbB, aoff, boff, af[0], bfr[0]);
#pragma unroll
    for (int ks = 0; ks < 4; ks++) {
        int cur = ks & 1;
        if (ks < 3)
            load_frags<MT>(ks + 1, sa, sbB, aoff, boff, af[cur ^ 1], bfr[cur ^ 1]);
#pragma unroll
        for (int mt = 0; mt < MT; mt++)
#pragma unroll
            for (int nt = 0; nt < 8; nt++)
                mma_f16(acc[mt][nt], af[cur][mt],
                        bfr[cur][nt >> 1][(nt & 1) * 2],
                        bfr[cur][nt >> 1][(nt & 1) * 2 + 1]);
    }
}

template <int MODE>
__global__ void __launch_bounds__(128, 2) k_gemm(float* __restrict__ out) {
    using C = Cfg<MODE>;
    extern __shared__ __align__(128) char smem[];
    uint32_t sbase = smem_u32(smem);
    int tid = threadIdx.x, lane = tid & 31, w = tid >> 5;
    int warp_m = w >> 1, warp_n = w & 1;

    int m0, n0;
    if (MODE == 0) { m0 = (blockIdx.x & 63) * 128; n0 = (blockIdx.x >> 6) * 128; }
    else           { m0 = blockIdx.x * 64;         n0 = 0; }

    float acc[C::MT][8][4];
#pragma unroll
    for (int a = 0; a < C::MT; a++)
#pragma unroll
        for (int b = 0; b < 8; b++)
#pragma unroll
            for (int c = 0; c < 4; c++) acc[a][b][c] = 0.f;

    uint32_t aoff = (uint32_t)(warp_m * (C::MT * 16) + (lane & 7) + ((lane >> 3) & 1) * 8) * PITCH_B
                  + (uint32_t)(lane >> 4) * 16;
    uint32_t boff = (uint32_t)(warp_n * 64 + (lane & 7) + ((lane >> 4) & 1) * 8) * PITCH_B
                  + (uint32_t)((lane >> 3) & 1) * 16;

    load_tile<MODE>(sbase, 0, 0, m0, n0, tid);
    load_tile<MODE>(sbase, 1, 1, m0, n0, tid);

    int stage = 0;
    for (int kt = 0; kt < C::NKT; kt++) {
        cp_wait<1>();
        __syncthreads();
        if (kt + 2 < C::NKT) {
            int s2 = stage + 2; if (s2 >= NSTAGE) s2 -= NSTAGE;
            load_tile<MODE>(sbase, s2, kt + 2, m0, n0, tid);
        } else {
            cp_commit();
        }
        uint32_t sa = sbase + stage * C::STAGE;
        compute_stage<C::MT>(sa, sa + C::TILE_A, acc, aoff, boff);
        if (++stage == NSTAGE) stage = 0;
    }

    if (MODE == 0) {
#pragma unroll
        for (int mt = 0; mt < C::MT; mt++) {
            int r0 = m0 + warp_m * 64 + mt * 16 + (lane >> 2);
#pragma unroll
            for (int nt = 0; nt < 8; nt++) {
                int col = n0 + warp_n * 64 + nt * 8 + (lane & 3) * 2;
                float2 v01 = make_float2(acc[mt][nt][0], acc[mt][nt][1]);
                float2 v23 = make_float2(acc[mt][nt][2], acc[mt][nt][3]);
                *reinterpret_cast<float2*>(out + (size_t)r0 * O_ + col) = v01;
                *reinterpret_cast<float2*>(out + (size_t)(r0 + 8) * O_ + col) = v23;
            }
        }
    } else {
#pragma unroll
        for (int mt = 0; mt < C::MT; mt++) {
            int t0 = m0 + warp_m * 32 + mt * 16 + (lane >> 2);
#pragma unroll
            for (int nt = 0; nt < 8; nt++) {
                int j = warp_n * 64 + nt * 8 + (lane & 3) * 2;
#pragma unroll
                for (int half = 0; half < 2; half++) {
                    int t = t0 + half * 8;
                    float wm = g_wmat[t * 8 + (j >> 4)];
                    __half2 hv(__float2half_rn(acc[mt][nt][half * 2 + 0] * wm),
                               __float2half_rn(acc[mt][nt][half * 2 + 1] * wm));
                    *reinterpret_cast<uint32_t*>(g_hw + (size_t)t * ER_ + j) =
                        *reinterpret_cast<uint32_t*>(&hv);
                }
            }
        }
    }
}

// ---------------- launch ------------------------------------------------------
extern "C" void kernel_launch(void* const* d_in, const int* in_sizes, int n_in,
                              void* d_out, int out_size) {
    const float* x  = (const float*)d_in[0];
    const float* W  = (const float*)d_in[1];
    const float* gw = (const float*)d_in[2];
    const float* A  = (const float*)d_in[3];
    const float* B  = (const float*)d_in[4];
    float* out = (float*)d_out;

    cudaFuncSetAttribute(k_router,  cudaFuncAttributeMaxDynamicSharedMemorySize, R_SMEM);
    cudaFuncSetAttribute(k_gemm<0>, cudaFuncAttributeMaxDynamicSharedMemorySize, Cfg<0>::SMEM);
    cudaFuncSetAttribute(k_gemm<1>, cudaFuncAttributeMaxDynamicSharedMemorySize, Cfg<1>::SMEM);

    k_prep<<<(PN_TOT + 255) / 256, 256>>>(x, W, A, B);
    k_router<<<T_ / 16, 128, R_SMEM>>>(x, gw);
    k_gemm<1><<<T_ / 64, 128, Cfg<1>::SMEM>>>(nullptr);
    k_gemm<0><<<(T_ / 128) * (O_ / 128), 128, Cfg<0>::SMEM>>>(out);
}